// round 2
// baseline (speedup 1.0000x reference)
#include <cuda_runtime.h>
#include <cstdint>

// Problem constants (fixed shapes per reference)
#define DIN    768
#define DSAE   16384
#define TDIM   12
#define KTOP   64
#define KBASIS 3
#define BSZ    1024
#define KDIM   (TDIM * DIN)   // 9216

// ---------------------------------------------------------------------------
// Device scratch (static: no runtime allocation allowed)
// ---------------------------------------------------------------------------
__device__ float g_pre[(size_t)BSZ * DSAE];      // 64 MB: encoder pre-activations
__device__ int   g_idx[BSZ * KTOP];              // top-k indices per row
__device__ float g_val[BSZ * KTOP];              // top-k relu'd values per row

// ---------------------------------------------------------------------------
// Kernel 1: SGEMM  pre[1024,16384] = x[1024,9216] @ W_enc[9216,16384] + b_enc
// 128x128x16 tile, 8x8 microtile, 256 threads, float4 loads.
// TWO-LEVEL ACCUMULATION: each 16-wide k-tile sums into fresh t[8][8], merged
// once per tile into acc[8][8]. Rounding error sigma ~1e-6 (vs ~4e-6 for a
// single sequential fp32 chain) -> top-k boundary flips vs the fp32 reference
// become dominated by the reference's own noise, not ours.
// ---------------------------------------------------------------------------
__global__ __launch_bounds__(256, 1)
void sgemm_kernel(const float* __restrict__ A,
                  const float* __restrict__ Bm,
                  const float* __restrict__ bias)
{
    const int N = DSAE, K = KDIM;
    __shared__ float As[16][128];   // transposed A tile
    __shared__ float Bs[16][128];

    const int tid  = threadIdx.x;
    const int bx   = blockIdx.x;    // N tile
    const int by   = blockIdx.y;    // M tile
    const int trow = tid >> 4;      // 0..15
    const int tcol = tid & 15;      // 0..15

    const float* Ablk = A  + (size_t)by * 128 * K;
    const float* Bblk = Bm + (size_t)bx * 128;

    float acc[8][8];
#pragma unroll
    for (int i = 0; i < 8; i++)
#pragma unroll
        for (int j = 0; j < 8; j++) acc[i][j] = 0.f;

    for (int k0 = 0; k0 < K; k0 += 16) {
#pragma unroll
        for (int i = 0; i < 2; i++) {
            const int l  = tid + i * 256;       // float4 id, 0..511
            // A tile: 128 rows x 16 cols
            const int ar = l >> 2;              // 0..127
            const int ac = (l & 3) << 2;        // 0,4,8,12
            float4 va = *(const float4*)(Ablk + (size_t)ar * K + k0 + ac);
            As[ac + 0][ar] = va.x;
            As[ac + 1][ar] = va.y;
            As[ac + 2][ar] = va.z;
            As[ac + 3][ar] = va.w;
            // B tile: 16 rows x 128 cols
            const int br = l >> 5;              // 0..15
            const int bc = (l & 31) << 2;       // 0..124
            *(float4*)(&Bs[br][bc]) =
                *(const float4*)(Bblk + (size_t)(k0 + br) * N + bc);
        }
        __syncthreads();

        // fresh tile accumulator (two-level accumulation for accuracy)
        float t[8][8];
#pragma unroll
        for (int i = 0; i < 8; i++)
#pragma unroll
            for (int j = 0; j < 8; j++) t[i][j] = 0.f;

#pragma unroll
        for (int kk = 0; kk < 16; kk++) {
            float ra[8], rb[8];
            *(float4*)(&ra[0]) = *(const float4*)(&As[kk][trow * 8 + 0]);
            *(float4*)(&ra[4]) = *(const float4*)(&As[kk][trow * 8 + 4]);
            *(float4*)(&rb[0]) = *(const float4*)(&Bs[kk][tcol * 8 + 0]);
            *(float4*)(&rb[4]) = *(const float4*)(&Bs[kk][tcol * 8 + 4]);
#pragma unroll
            for (int i = 0; i < 8; i++)
#pragma unroll
                for (int j = 0; j < 8; j++)
                    t[i][j] = fmaf(ra[i], rb[j], t[i][j]);
        }

        // merge tile sum into master accumulator
#pragma unroll
        for (int i = 0; i < 8; i++)
#pragma unroll
            for (int j = 0; j < 8; j++)
                acc[i][j] += t[i][j];

        __syncthreads();
    }

    // epilogue: + bias, store to g_pre
#pragma unroll
    for (int i = 0; i < 8; i++) {
        const size_t row = (size_t)by * 128 + trow * 8 + i;
#pragma unroll
        for (int j = 0; j < 8; j += 4) {
            const int col = bx * 128 + tcol * 8 + j;
            float4 o;
            o.x = acc[i][j + 0] + bias[col + 0];
            o.y = acc[i][j + 1] + bias[col + 1];
            o.z = acc[i][j + 2] + bias[col + 2];
            o.w = acc[i][j + 3] + bias[col + 3];
            *(float4*)(&g_pre[row * N + col]) = o;
        }
    }
}

// ---------------------------------------------------------------------------
// Kernel 2: per-row top-64 radix select + z scatter
// One block (256 threads) per row; row cached as monotone uint keys in smem.
// ---------------------------------------------------------------------------
__device__ __forceinline__ unsigned f2k(float f) {
    unsigned u = __float_as_uint(f);
    return (u & 0x80000000u) ? ~u : (u | 0x80000000u);
}
__device__ __forceinline__ float k2f(unsigned k) {
    unsigned u = (k & 0x80000000u) ? (k & 0x7fffffffu) : ~k;
    return __uint_as_float(u);
}

__global__ void topk_kernel(float* __restrict__ z_out)
{
    extern __shared__ unsigned skeys[];          // DSAE * 4 = 64 KB
    __shared__ unsigned hist[256];
    __shared__ unsigned eqmask[DSAE / 32];       // 2 KB, slow path only
    __shared__ int s_digit, s_take, s_ceq, s_cnt, s_allq;
    __shared__ int   s_idx[KTOP];
    __shared__ float s_val[KTOP];

    const int b   = blockIdx.x;
    const int tid = threadIdx.x;
    const float* row = g_pre + (size_t)b * DSAE;

    for (int e = tid; e < DSAE; e += 256) skeys[e] = f2k(row[e]);
    __syncthreads();

    unsigned prefix = 0;
    int k_rem = KTOP;
#pragma unroll
    for (int r = 0; r < 4; r++) {
        const int shift = 24 - 8 * r;
        hist[tid] = 0;
        __syncthreads();
        for (int e = tid; e < DSAE; e += 256) {
            const unsigned key = skeys[e];
            if (r == 0 || (key >> (shift + 8)) == prefix)
                atomicAdd(&hist[(key >> shift) & 255u], 1u);
        }
        __syncthreads();
        if (tid == 0) {
            int c = 0, d;
            for (d = 255; d > 0; --d) {
                const int h = (int)hist[d];
                if (c + h >= k_rem) break;
                c += h;
            }
            s_digit = d;
            s_take  = k_rem - c;       // how many to take from bin d
            s_ceq   = (int)hist[d];    // bin population
        }
        __syncthreads();
        prefix = (prefix << 8) | (unsigned)s_digit;
        k_rem  = s_take;
        __syncthreads();
    }
    const unsigned kth = prefix;       // exact 64th-largest key
    const int take_eq  = k_rem;        // #equal-to-kth entries to include

    if (tid == 0) { s_allq = (s_ceq == take_eq); s_cnt = 0; }
    __syncthreads();

    if (!s_allq) {   // rare tie path: pick lowest-index equals (matches jax top_k)
        for (int i = tid; i < DSAE / 32; i += 256) eqmask[i] = 0u;
        __syncthreads();
        if (tid == 0) {
            int taken = 0;
            for (int e = 0; e < DSAE && taken < take_eq; e++)
                if (skeys[e] == kth) { eqmask[e >> 5] |= 1u << (e & 31); taken++; }
        }
        __syncthreads();
    }

    for (int e = tid; e < DSAE; e += 256) {
        const unsigned key = skeys[e];
        const bool sel = (key > kth) ||
                         (key == kth && (s_allq || ((eqmask[e >> 5] >> (e & 31)) & 1u)));
        const float v = sel ? fmaxf(k2f(key), 0.f) : 0.f;
        z_out[(size_t)b * DSAE + e] = v;
        if (sel) {
            const int p = atomicAdd(&s_cnt, 1);
            if (p < KTOP) { s_idx[p] = e; s_val[p] = v; }
        }
    }
    __syncthreads();
    if (tid < KTOP) {
        g_idx[b * KTOP + tid] = s_idx[tid];
        g_val[b * KTOP + tid] = s_val[tid];
    }
}

// ---------------------------------------------------------------------------
// Kernel 3: sparse decode + basis combine + x_hat + loss
// One block per batch row. acc[k][dd], d = tid + dd*256 (768 = 3*256).
// ---------------------------------------------------------------------------
__global__ __launch_bounds__(256)
void decode_kernel(const float* __restrict__ x,
                   const float* __restrict__ Wb,
                   const float* __restrict__ alpha,
                   const float* __restrict__ b_dec,
                   float* __restrict__ xhat,
                   float* __restrict__ loss)
{
    __shared__ int   sidx[KTOP];
    __shared__ float sval[KTOP];
    __shared__ float salpha[TDIM * KBASIS];
    __shared__ float warpsum[8];

    const int b = blockIdx.x, tid = threadIdx.x;
    if (tid < KTOP)          { sidx[tid] = g_idx[b * KTOP + tid]; sval[tid] = g_val[b * KTOP + tid]; }
    if (tid < TDIM * KBASIS) { salpha[tid] = alpha[tid]; }
    __syncthreads();

    float acc[KBASIS][3];
#pragma unroll
    for (int k3 = 0; k3 < KBASIS; k3++)
#pragma unroll
        for (int dd = 0; dd < 3; dd++) acc[k3][dd] = 0.f;

    for (int j = 0; j < KTOP; j++) {
        const float v = sval[j];
        if (v == 0.f) continue;                     // uniform branch per block
        const int s = sidx[j];
        const float* wr = Wb + (size_t)s * DIN;
#pragma unroll
        for (int k3 = 0; k3 < KBASIS; k3++) {
            const float* w = wr + (size_t)k3 * DSAE * DIN;
#pragma unroll
            for (int dd = 0; dd < 3; dd++)
                acc[k3][dd] = fmaf(v, __ldg(&w[tid + dd * 256]), acc[k3][dd]);
        }
    }

    float lsum = 0.f;
#pragma unroll
    for (int t = 0; t < TDIM; t++) {
        const float a0 = salpha[t * KBASIS + 0];
        const float a1 = salpha[t * KBASIS + 1];
        const float a2 = salpha[t * KBASIS + 2];
#pragma unroll
        for (int dd = 0; dd < 3; dd++) {
            const int d = tid + dd * 256;
            const size_t off = ((size_t)b * TDIM + t) * DIN + d;
            const float xh = a0 * acc[0][dd] + a1 * acc[1][dd] + a2 * acc[2][dd]
                           + b_dec[t * DIN + d];
            xhat[off] = xh;
            const float diff = xh - x[off];
            lsum = fmaf(diff, diff, lsum);
        }
    }

    // block reduce -> atomic loss
#pragma unroll
    for (int o = 16; o > 0; o >>= 1) lsum += __shfl_down_sync(0xffffffffu, lsum, o);
    if ((tid & 31) == 0) warpsum[tid >> 5] = lsum;
    __syncthreads();
    if (tid == 0) {
        float s = 0.f;
#pragma unroll
        for (int w = 0; w < 8; w++) s += warpsum[w];
        atomicAdd(loss, s * (1.0f / (float)(BSZ * TDIM)));
    }
}

// ---------------------------------------------------------------------------
// kernel_launch: inputs = [x, W_enc, b_enc, W_base, alpha, b_dec, k]
// output (f32, concat): [recon_loss(1), x_hat(B*T*DIN), z(B*DSAE)]
// ---------------------------------------------------------------------------
extern "C" void kernel_launch(void* const* d_in, const int* in_sizes, int n_in,
                              void* d_out, int out_size)
{
    const float* x      = (const float*)d_in[0];
    const float* W_enc  = (const float*)d_in[1];
    const float* b_enc  = (const float*)d_in[2];
    const float* W_base = (const float*)d_in[3];
    const float* alpha  = (const float*)d_in[4];
    const float* b_dec  = (const float*)d_in[5];
    // d_in[6] = k (fixed at 64 for this problem's shapes)

    float* out  = (float*)d_out;
    float* loss = out;
    float* xhat = out + 1;
    float* z    = out + 1 + (size_t)BSZ * TDIM * DIN;

    cudaMemsetAsync(loss, 0, sizeof(float));

    dim3 gemm_grid(DSAE / 128, BSZ / 128);   // (128, 8)
    sgemm_kernel<<<gemm_grid, 256>>>(x, W_enc, b_enc);

    cudaFuncSetAttribute(topk_kernel,
                         cudaFuncAttributeMaxDynamicSharedMemorySize,
                         DSAE * (int)sizeof(unsigned));
    topk_kernel<<<BSZ, 256, DSAE * sizeof(unsigned)>>>(z);

    decode_kernel<<<BSZ, 256>>>(x, W_base, alpha, b_dec, xhat, loss);
}

// round 4
// speedup vs baseline: 1.4609x; 1.4609x over previous
#include <cuda_runtime.h>
#include <cstdint>

// Problem constants (fixed shapes per reference)
#define DIN    768
#define DSAE   16384
#define TDIM   12
#define KTOP   64
#define KBASIS 3
#define BSZ    1024
#define KDIM   9216

// GEMM tiling
#define KCH    16
#define NCHUNK (KDIM / KCH)       // 576
#define MERGE_PERIOD 16           // chunks per two-level merge (K=256)

// smem float offsets (per design: A pitch 24, B pitch 136)
#define A_STAGE_F   3072          // 128*24
#define B_STAGE_F   2176          // 16*136
#define SM_AH       0
#define SM_AL       (2 * A_STAGE_F)                 // 6144
#define SM_BH       (4 * A_STAGE_F)                 // 12288
#define SM_BL       (4 * A_STAGE_F + 2 * B_STAGE_F) // 16640
#define SM_TOTAL_F  (4 * A_STAGE_F + 4 * B_STAGE_F) // 20992 floats = 83968 B

// ---------------------------------------------------------------------------
// Device scratch
// ---------------------------------------------------------------------------
__device__ float g_pre[(size_t)BSZ * DSAE];      // 64 MB
__device__ int   g_idx[BSZ * KTOP];
__device__ float g_val[BSZ * KTOP];

// ---------------------------------------------------------------------------
// helpers
// ---------------------------------------------------------------------------
__device__ __forceinline__ float tf32r(float x) {
    uint32_t r;
    asm("cvt.rna.tf32.f32 %0, %1;" : "=r"(r) : "f"(x));
    return __uint_as_float(r);
}

__device__ __forceinline__ void mma8(float* c, const uint32_t* a, const uint32_t* b) {
    asm volatile(
        "mma.sync.aligned.m16n8k8.row.col.f32.tf32.tf32.f32 "
        "{%0,%1,%2,%3}, {%4,%5,%6,%7}, {%8,%9}, {%0,%1,%2,%3};\n"
        : "+f"(c[0]), "+f"(c[1]), "+f"(c[2]), "+f"(c[3])
        : "r"(a[0]), "r"(a[1]), "r"(a[2]), "r"(a[3]), "r"(b[0]), "r"(b[1]));
}

// ---------------------------------------------------------------------------
// Kernel 1: tf32x3 mma.sync GEMM
//   pre[1024,16384] = x[1024,9216] @ W_enc[9216,16384] + b_enc
// CTA 128x128, 8 warps (2Mx4N), warp tile 64x32. K-chunk 16, 2-stage smem
// pipeline, inline fp32->(tf32 hi, tf32 lo) split in the producer.
// Passes per k-step: hi*hi + hi*lo + lo*hi  (~fp32 accuracy).
// Two-level accumulation: tile acc merged into master every 16 chunks.
// ---------------------------------------------------------------------------
__global__ __launch_bounds__(256)
void enc_gemm(const float* __restrict__ A,
              const float* __restrict__ B,
              const float* __restrict__ bias)
{
    extern __shared__ float sm[];

    const int tid  = threadIdx.x;
    const int wid  = tid >> 5;
    const int lane = tid & 31;
    const int by   = blockIdx.x;   // M tile (0..7)  -- fast-varying for B reuse
    const int bx   = blockIdx.y;   // N tile (0..127)

    const int wm = wid >> 2;       // 0..1  (64-row half)
    const int wn = wid & 3;        // 0..3  (32-col quarter)
    const int g  = lane >> 2;      // 0..7
    const int t  = lane & 3;       // 0..3

    // producer mapping
    const int am = tid >> 1;             // A row 0..127
    const int aks = tid & 1;             // A k-half (8 floats)
    const int bk = tid >> 4;             // B k-row 0..15
    const int bj = tid & 15;             // B col group (4 floats)

    const float* Ag = A + (size_t)by * 128 * KDIM + (size_t)am * KDIM + aks * 8;
    const float* Bg = B + (size_t)bx * 128 + bj * 4;

    float accm[4][4][4];
    float acct[4][4][4];
#pragma unroll
    for (int mt = 0; mt < 4; mt++)
#pragma unroll
        for (int nt = 0; nt < 4; nt++)
#pragma unroll
            for (int q = 0; q < 4; q++) { accm[mt][nt][q] = 0.f; acct[mt][nt][q] = 0.f; }

    float4 av0, av1, bv0, bv1;

    // ---- prologue: load + split + store chunk 0 ----
    av0 = *(const float4*)(Ag);
    av1 = *(const float4*)(Ag + 4);
    {
        const float* bp = Bg + (size_t)bk * DSAE;
        bv0 = *(const float4*)(bp);
        bv1 = *(const float4*)(bp + 64);
    }
#define SPLIT_STS(stage)                                                          \
    do {                                                                          \
        float va[8] = {av0.x, av0.y, av0.z, av0.w, av1.x, av1.y, av1.z, av1.w};   \
        const int abase = am * 24 + aks * 8;                                      \
        float* AH = sm + SM_AH + (stage) * A_STAGE_F;                             \
        float* AL = sm + SM_AL + (stage) * A_STAGE_F;                             \
        _Pragma("unroll")                                                         \
        for (int i = 0; i < 4; i++) {                                             \
            float h0 = tf32r(va[i]),     l0 = tf32r(va[i] - h0);                  \
            float h1 = tf32r(va[i + 4]), l1 = tf32r(va[i + 4] - h1);              \
            *(float2*)(AH + abase + i * 2) = make_float2(h0, h1);                 \
            *(float2*)(AL + abase + i * 2) = make_float2(l0, l1);                 \
        }                                                                         \
        float* BH = sm + SM_BH + (stage) * B_STAGE_F;                             \
        float* BL = sm + SM_BL + (stage) * B_STAGE_F;                             \
        {                                                                         \
            float4 h, l;                                                          \
            h.x = tf32r(bv0.x); l.x = tf32r(bv0.x - h.x);                         \
            h.y = tf32r(bv0.y); l.y = tf32r(bv0.y - h.y);                         \
            h.z = tf32r(bv0.z); l.z = tf32r(bv0.z - h.z);                         \
            h.w = tf32r(bv0.w); l.w = tf32r(bv0.w - h.w);                         \
            *(float4*)(BH + bk * 136 + bj * 4) = h;                               \
            *(float4*)(BL + bk * 136 + bj * 4) = l;                               \
            h.x = tf32r(bv1.x); l.x = tf32r(bv1.x - h.x);                         \
            h.y = tf32r(bv1.y); l.y = tf32r(bv1.y - h.y);                         \
            h.z = tf32r(bv1.z); l.z = tf32r(bv1.z - h.z);                         \
            h.w = tf32r(bv1.w); l.w = tf32r(bv1.w - h.w);                         \
            *(float4*)(BH + bk * 136 + 64 + bj * 4) = h;                          \
            *(float4*)(BL + bk * 136 + 64 + bj * 4) = l;                          \
        }                                                                         \
    } while (0)

    SPLIT_STS(0);
    __syncthreads();

    // ---- main loop ----
    for (int c = 0; c < NCHUNK; c++) {
        const int st = c & 1;

        if (c + 1 < NCHUNK) {                   // prefetch next chunk into regs
            const float* ap = Ag + (c + 1) * KCH;
            av0 = *(const float4*)(ap);
            av1 = *(const float4*)(ap + 4);
            const float* bp = Bg + (size_t)((c + 1) * KCH + bk) * DSAE;
            bv0 = *(const float4*)(bp);
            bv1 = *(const float4*)(bp + 64);
        }

        // ---- compute chunk c from stage st ----
        {
            const float* AHs = sm + SM_AH + st * A_STAGE_F;
            const float* ALs = sm + SM_AL + st * A_STAGE_F;
            const float* BHs = sm + SM_BH + st * B_STAGE_F;
            const float* BLs = sm + SM_BL + st * B_STAGE_F;
#pragma unroll
            for (int ks = 0; ks < 2; ks++) {
                uint32_t Afh[4][4], Afl[4][4], Bfh[4][2], Bfl[4][2];
#pragma unroll
                for (int mt = 0; mt < 4; mt++) {
                    const int r0 = (wm * 64 + mt * 16 + g) * 24 + ks * 8 + t * 2;
                    float2 p0 = *(const float2*)(AHs + r0);
                    float2 p1 = *(const float2*)(AHs + r0 + 192);   // +8 rows
                    Afh[mt][0] = __float_as_uint(p0.x);
                    Afh[mt][1] = __float_as_uint(p1.x);
                    Afh[mt][2] = __float_as_uint(p0.y);
                    Afh[mt][3] = __float_as_uint(p1.y);
                    p0 = *(const float2*)(ALs + r0);
                    p1 = *(const float2*)(ALs + r0 + 192);
                    Afl[mt][0] = __float_as_uint(p0.x);
                    Afl[mt][1] = __float_as_uint(p1.x);
                    Afl[mt][2] = __float_as_uint(p0.y);
                    Afl[mt][3] = __float_as_uint(p1.y);
                }
#pragma unroll
                for (int nt = 0; nt < 4; nt++) {
                    const int cb = (ks * 8 + t) * 136 + wn * 32 + nt * 8 + g;
                    Bfh[nt][0] = __float_as_uint(BHs[cb]);
                    Bfh[nt][1] = __float_as_uint(BHs[cb + 4 * 136]);
                    Bfl[nt][0] = __float_as_uint(BLs[cb]);
                    Bfl[nt][1] = __float_as_uint(BLs[cb + 4 * 136]);
                }
#pragma unroll
                for (int mt = 0; mt < 4; mt++)
#pragma unroll
                    for (int nt = 0; nt < 4; nt++) {
                        mma8(acct[mt][nt], Afh[mt], Bfh[nt]);
                        mma8(acct[mt][nt], Afh[mt], Bfl[nt]);
                        mma8(acct[mt][nt], Afl[mt], Bfh[nt]);
                    }
            }
        }

        // two-level merge every MERGE_PERIOD chunks (576 % 16 == 0)
        if ((c & (MERGE_PERIOD - 1)) == (MERGE_PERIOD - 1)) {
#pragma unroll
            for (int mt = 0; mt < 4; mt++)
#pragma unroll
                for (int nt = 0; nt < 4; nt++)
#pragma unroll
                    for (int q = 0; q < 4; q++) {
                        accm[mt][nt][q] += acct[mt][nt][q];
                        acct[mt][nt][q] = 0.f;
                    }
        }

        if (c + 1 < NCHUNK) SPLIT_STS((c + 1) & 1);
        __syncthreads();
    }

    // ---- epilogue: +bias, store to g_pre ----
#pragma unroll
    for (int nt = 0; nt < 4; nt++) {
        const int col = bx * 128 + wn * 32 + nt * 8 + 2 * t;
        const float b0 = bias[col], b1 = bias[col + 1];
#pragma unroll
        for (int mt = 0; mt < 4; mt++) {
            const size_t r0 = (size_t)(by * 128 + wm * 64 + mt * 16 + g) * DSAE + col;
            *(float2*)(g_pre + r0) =
                make_float2(accm[mt][nt][0] + b0, accm[mt][nt][1] + b1);
            *(float2*)(g_pre + r0 + (size_t)8 * DSAE) =
                make_float2(accm[mt][nt][2] + b0, accm[mt][nt][3] + b1);
        }
    }
}

// ---------------------------------------------------------------------------
// Kernel 2: per-row top-64 radix select + z scatter (unchanged, passing)
// ---------------------------------------------------------------------------
__device__ __forceinline__ unsigned f2k(float f) {
    unsigned u = __float_as_uint(f);
    return (u & 0x80000000u) ? ~u : (u | 0x80000000u);
}
__device__ __forceinline__ float k2f(unsigned k) {
    unsigned u = (k & 0x80000000u) ? (k & 0x7fffffffu) : ~k;
    return __uint_as_float(u);
}

__global__ void topk_kernel(float* __restrict__ z_out)
{
    extern __shared__ unsigned skeys[];          // DSAE * 4 = 64 KB
    __shared__ unsigned hist[256];
    __shared__ unsigned eqmask[DSAE / 32];
    __shared__ int s_digit, s_take, s_ceq, s_cnt, s_allq;
    __shared__ int   s_idx[KTOP];
    __shared__ float s_val[KTOP];

    const int b   = blockIdx.x;
    const int tid = threadIdx.x;
    const float* row = g_pre + (size_t)b * DSAE;

    for (int e = tid; e < DSAE; e += 256) skeys[e] = f2k(row[e]);
    __syncthreads();

    unsigned prefix = 0;
    int k_rem = KTOP;
#pragma unroll
    for (int r = 0; r < 4; r++) {
        const int shift = 24 - 8 * r;
        hist[tid] = 0;
        __syncthreads();
        for (int e = tid; e < DSAE; e += 256) {
            const unsigned key = skeys[e];
            if (r == 0 || (key >> (shift + 8)) == prefix)
                atomicAdd(&hist[(key >> shift) & 255u], 1u);
        }
        __syncthreads();
        if (tid == 0) {
            int c = 0, d;
            for (d = 255; d > 0; --d) {
                const int h = (int)hist[d];
                if (c + h >= k_rem) break;
                c += h;
            }
            s_digit = d;
            s_take  = k_rem - c;
            s_ceq   = (int)hist[d];
        }
        __syncthreads();
        prefix = (prefix << 8) | (unsigned)s_digit;
        k_rem  = s_take;
        __syncthreads();
    }
    const unsigned kth = prefix;
    const int take_eq  = k_rem;

    if (tid == 0) { s_allq = (s_ceq == take_eq); s_cnt = 0; }
    __syncthreads();

    if (!s_allq) {
        for (int i = tid; i < DSAE / 32; i += 256) eqmask[i] = 0u;
        __syncthreads();
        if (tid == 0) {
            int taken = 0;
            for (int e = 0; e < DSAE && taken < take_eq; e++)
                if (skeys[e] == kth) { eqmask[e >> 5] |= 1u << (e & 31); taken++; }
        }
        __syncthreads();
    }

    for (int e = tid; e < DSAE; e += 256) {
        const unsigned key = skeys[e];
        const bool sel = (key > kth) ||
                         (key == kth && (s_allq || ((eqmask[e >> 5] >> (e & 31)) & 1u)));
        const float v = sel ? fmaxf(k2f(key), 0.f) : 0.f;
        z_out[(size_t)b * DSAE + e] = v;
        if (sel) {
            const int p = atomicAdd(&s_cnt, 1);
            if (p < KTOP) { s_idx[p] = e; s_val[p] = v; }
        }
    }
    __syncthreads();
    if (tid < KTOP) {
        g_idx[b * KTOP + tid] = s_idx[tid];
        g_val[b * KTOP + tid] = s_val[tid];
    }
}

// ---------------------------------------------------------------------------
// Kernel 3: sparse decode + basis combine + x_hat + loss (unchanged, passing)
// ---------------------------------------------------------------------------
__global__ __launch_bounds__(256)
void decode_kernel(const float* __restrict__ x,
                   const float* __restrict__ Wb,
                   const float* __restrict__ alpha,
                   const float* __restrict__ b_dec,
                   float* __restrict__ xhat,
                   float* __restrict__ loss)
{
    __shared__ int   sidx[KTOP];
    __shared__ float sval[KTOP];
    __shared__ float salpha[TDIM * KBASIS];
    __shared__ float warpsum[8];

    const int b = blockIdx.x, tid = threadIdx.x;
    if (tid < KTOP)          { sidx[tid] = g_idx[b * KTOP + tid]; sval[tid] = g_val[b * KTOP + tid]; }
    if (tid < TDIM * KBASIS) { salpha[tid] = alpha[tid]; }
    __syncthreads();

    float acc[KBASIS][3];
#pragma unroll
    for (int k3 = 0; k3 < KBASIS; k3++)
#pragma unroll
        for (int dd = 0; dd < 3; dd++) acc[k3][dd] = 0.f;

    for (int j = 0; j < KTOP; j++) {
        const float v = sval[j];
        if (v == 0.f) continue;
        const int s = sidx[j];
        const float* wr = Wb + (size_t)s * DIN;
#pragma unroll
        for (int k3 = 0; k3 < KBASIS; k3++) {
            const float* w = wr + (size_t)k3 * DSAE * DIN;
#pragma unroll
            for (int dd = 0; dd < 3; dd++)
                acc[k3][dd] = fmaf(v, __ldg(&w[tid + dd * 256]), acc[k3][dd]);
        }
    }

    float lsum = 0.f;
#pragma unroll
    for (int t = 0; t < TDIM; t++) {
        const float a0 = salpha[t * KBASIS + 0];
        const float a1 = salpha[t * KBASIS + 1];
        const float a2 = salpha[t * KBASIS + 2];
#pragma unroll
        for (int dd = 0; dd < 3; dd++) {
            const int d = tid + dd * 256;
            const size_t off = ((size_t)b * TDIM + t) * DIN + d;
            const float xh = a0 * acc[0][dd] + a1 * acc[1][dd] + a2 * acc[2][dd]
                           + b_dec[t * DIN + d];
            xhat[off] = xh;
            const float diff = xh - x[off];
            lsum = fmaf(diff, diff, lsum);
        }
    }

#pragma unroll
    for (int o = 16; o > 0; o >>= 1) lsum += __shfl_down_sync(0xffffffffu, lsum, o);
    if ((tid & 31) == 0) warpsum[tid >> 5] = lsum;
    __syncthreads();
    if (tid == 0) {
        float s = 0.f;
#pragma unroll
        for (int w = 0; w < 8; w++) s += warpsum[w];
        atomicAdd(loss, s * (1.0f / (float)(BSZ * TDIM)));
    }
}

// ---------------------------------------------------------------------------
// kernel_launch: inputs = [x, W_enc, b_enc, W_base, alpha, b_dec, k]
// output (f32, concat): [recon_loss(1), x_hat(B*T*DIN), z(B*DSAE)]
// ---------------------------------------------------------------------------
extern "C" void kernel_launch(void* const* d_in, const int* in_sizes, int n_in,
                              void* d_out, int out_size)
{
    const float* x      = (const float*)d_in[0];
    const float* W_enc  = (const float*)d_in[1];
    const float* b_enc  = (const float*)d_in[2];
    const float* W_base = (const float*)d_in[3];
    const float* alpha  = (const float*)d_in[4];
    const float* b_dec  = (const float*)d_in[5];

    float* out  = (float*)d_out;
    float* loss = out;
    float* xhat = out + 1;
    float* z    = out + 1 + (size_t)BSZ * TDIM * DIN;

    cudaMemsetAsync(loss, 0, sizeof(float));

    const int gemm_smem = SM_TOTAL_F * (int)sizeof(float);   // 83968 B
    cudaFuncSetAttribute(enc_gemm,
                         cudaFuncAttributeMaxDynamicSharedMemorySize, gemm_smem);
    dim3 gemm_grid(BSZ / 128, DSAE / 128);   // (8, 128): M fast-varying
    enc_gemm<<<gemm_grid, 256, gemm_smem>>>(x, W_enc, b_enc);

    cudaFuncSetAttribute(topk_kernel,
                         cudaFuncAttributeMaxDynamicSharedMemorySize,
                         DSAE * (int)sizeof(unsigned));
    topk_kernel<<<BSZ, 256, DSAE * sizeof(unsigned)>>>(z);

    decode_kernel<<<BSZ, 256>>>(x, W_base, alpha, b_dec, xhat, loss);
}

// round 5
// speedup vs baseline: 2.8621x; 1.9591x over previous
#include <cuda_runtime.h>
#include <cstdint>

// Problem constants (fixed shapes per reference)
#define DIN    768
#define DSAE   16384
#define TDIM   12
#define KTOP   64
#define KBASIS 3
#define BSZ    1024
#define KDIM   9216

// GEMM tiling
#define KCH    16
#define NCHUNK (KDIM / KCH)       // 576

// smem float offsets (A pitch 24, B pitch 136), single precision pass
#define A_STAGE_F   3072          // 128*24
#define B_STAGE_F   2176          // 16*136
#define SM_AH       0
#define SM_BH       (2 * A_STAGE_F)                 // 6144
#define SM_TOTAL_F  (2 * A_STAGE_F + 2 * B_STAGE_F) // 10496 floats = 41984 B

// band half-width around approx 64th value (~28 sigma of tf32 1-pass noise)
#define DELTA  0.02f
#define MAXB   64

// ---------------------------------------------------------------------------
// Device scratch
// ---------------------------------------------------------------------------
__device__ float g_pre[(size_t)BSZ * DSAE];      // 64 MB
__device__ int   g_idx[BSZ * KTOP];
__device__ float g_val[BSZ * KTOP];
__device__ int   g_scnt[BSZ];                    // certain count per row
__device__ int   g_bcnt[BSZ];                    // band count per row
__device__ int   g_bidx[BSZ][MAXB];              // band candidate indices
__device__ float g_bval[BSZ][MAXB];              // exact rescored values

// ---------------------------------------------------------------------------
// helpers
// ---------------------------------------------------------------------------
__device__ __forceinline__ float tf32r(float x) {
    uint32_t r;
    asm("cvt.rna.tf32.f32 %0, %1;" : "=r"(r) : "f"(x));
    return __uint_as_float(r);
}

__device__ __forceinline__ void mma8(float* c, const uint32_t* a, const uint32_t* b) {
    asm volatile(
        "mma.sync.aligned.m16n8k8.row.col.f32.tf32.tf32.f32 "
        "{%0,%1,%2,%3}, {%4,%5,%6,%7}, {%8,%9}, {%0,%1,%2,%3};\n"
        : "+f"(c[0]), "+f"(c[1]), "+f"(c[2]), "+f"(c[3])
        : "r"(a[0]), "r"(a[1]), "r"(a[2]), "r"(a[3]), "r"(b[0]), "r"(b[1]));
}

// ---------------------------------------------------------------------------
// Kernel 1: single-pass tf32 mma.sync GEMM (approximate pre; selection fixed
// up later by exact band rescoring).
//   pre[1024,16384] = x[1024,9216] @ W_enc[9216,16384] + b_enc
// CTA 128x128, 8 warps (2Mx4N), warp tile 64x32, K-chunk 16, 2-stage pipeline.
// ---------------------------------------------------------------------------
__global__ __launch_bounds__(256)
void enc_gemm(const float* __restrict__ A,
              const float* __restrict__ B,
              const float* __restrict__ bias)
{
    extern __shared__ float sm[];

    const int tid  = threadIdx.x;
    const int wid  = tid >> 5;
    const int lane = tid & 31;
    const int by   = blockIdx.x;   // M tile (0..7)  -- fast-varying for B reuse
    const int bx   = blockIdx.y;   // N tile (0..127)

    const int wm = wid >> 2;       // 0..1
    const int wn = wid & 3;        // 0..3
    const int g  = lane >> 2;      // 0..7
    const int t  = lane & 3;       // 0..3

    const int am  = tid >> 1;      // A row 0..127
    const int aks = tid & 1;       // A k-half
    const int bk  = tid >> 4;      // B k-row 0..15
    const int bj  = tid & 15;      // B col group

    const float* Ag = A + (size_t)by * 128 * KDIM + (size_t)am * KDIM + aks * 8;
    const float* Bg = B + (size_t)bx * 128 + bj * 4;

    float accm[4][4][4];
#pragma unroll
    for (int mt = 0; mt < 4; mt++)
#pragma unroll
        for (int nt = 0; nt < 4; nt++)
#pragma unroll
            for (int q = 0; q < 4; q++) accm[mt][nt][q] = 0.f;

    float4 av0, av1, bv0, bv1;

    av0 = *(const float4*)(Ag);
    av1 = *(const float4*)(Ag + 4);
    {
        const float* bp = Bg + (size_t)bk * DSAE;
        bv0 = *(const float4*)(bp);
        bv1 = *(const float4*)(bp + 64);
    }

#define CVT_STS(stage)                                                            \
    do {                                                                          \
        float va[8] = {av0.x, av0.y, av0.z, av0.w, av1.x, av1.y, av1.z, av1.w};   \
        const int abase = am * 24 + aks * 8;                                      \
        float* AH = sm + SM_AH + (stage) * A_STAGE_F;                             \
        _Pragma("unroll")                                                         \
        for (int i = 0; i < 4; i++)                                               \
            *(float2*)(AH + abase + i * 2) =                                      \
                make_float2(tf32r(va[i]), tf32r(va[i + 4]));                      \
        float* BH = sm + SM_BH + (stage) * B_STAGE_F;                             \
        float4 h;                                                                 \
        h.x = tf32r(bv0.x); h.y = tf32r(bv0.y);                                   \
        h.z = tf32r(bv0.z); h.w = tf32r(bv0.w);                                   \
        *(float4*)(BH + bk * 136 + bj * 4) = h;                                   \
        h.x = tf32r(bv1.x); h.y = tf32r(bv1.y);                                   \
        h.z = tf32r(bv1.z); h.w = tf32r(bv1.w);                                   \
        *(float4*)(BH + bk * 136 + 64 + bj * 4) = h;                              \
    } while (0)

    CVT_STS(0);
    __syncthreads();

    for (int c = 0; c < NCHUNK; c++) {
        const int st = c & 1;

        if (c + 1 < NCHUNK) {
            const float* ap = Ag + (c + 1) * KCH;
            av0 = *(const float4*)(ap);
            av1 = *(const float4*)(ap + 4);
            const float* bp = Bg + (size_t)((c + 1) * KCH + bk) * DSAE;
            bv0 = *(const float4*)(bp);
            bv1 = *(const float4*)(bp + 64);
        }

        {
            const float* AHs = sm + SM_AH + st * A_STAGE_F;
            const float* BHs = sm + SM_BH + st * B_STAGE_F;
#pragma unroll
            for (int ks = 0; ks < 2; ks++) {
                uint32_t Af[4][4], Bf[4][2];
#pragma unroll
                for (int mt = 0; mt < 4; mt++) {
                    const int r0 = (wm * 64 + mt * 16 + g) * 24 + ks * 8 + t * 2;
                    float2 p0 = *(const float2*)(AHs + r0);
                    float2 p1 = *(const float2*)(AHs + r0 + 192);   // +8 rows
                    Af[mt][0] = __float_as_uint(p0.x);
                    Af[mt][1] = __float_as_uint(p1.x);
                    Af[mt][2] = __float_as_uint(p0.y);
                    Af[mt][3] = __float_as_uint(p1.y);
                }
#pragma unroll
                for (int nt = 0; nt < 4; nt++) {
                    const int cb = (ks * 8 + t) * 136 + wn * 32 + nt * 8 + g;
                    Bf[nt][0] = __float_as_uint(BHs[cb]);
                    Bf[nt][1] = __float_as_uint(BHs[cb + 4 * 136]);
                }
#pragma unroll
                for (int mt = 0; mt < 4; mt++)
#pragma unroll
                    for (int nt = 0; nt < 4; nt++)
                        mma8(accm[mt][nt], Af[mt], Bf[nt]);
            }
        }

        if (c + 1 < NCHUNK) CVT_STS((c + 1) & 1);
        __syncthreads();
    }

    // ---- epilogue: +bias, store to g_pre ----
#pragma unroll
    for (int nt = 0; nt < 4; nt++) {
        const int col = bx * 128 + wn * 32 + nt * 8 + 2 * t;
        const float b0 = bias[col], b1 = bias[col + 1];
#pragma unroll
        for (int mt = 0; mt < 4; mt++) {
            const size_t r0 = (size_t)(by * 128 + wm * 64 + mt * 16 + g) * DSAE + col;
            *(float2*)(g_pre + r0) =
                make_float2(accm[mt][nt][0] + b0, accm[mt][nt][1] + b1);
            *(float2*)(g_pre + r0 + (size_t)8 * DSAE) =
                make_float2(accm[mt][nt][2] + b0, accm[mt][nt][3] + b1);
        }
    }
}

// ---------------------------------------------------------------------------
// Kernel 2: per-row top-64 radix select on approx pre + certain/band split
// ---------------------------------------------------------------------------
__device__ __forceinline__ unsigned f2k(float f) {
    unsigned u = __float_as_uint(f);
    return (u & 0x80000000u) ? ~u : (u | 0x80000000u);
}
__device__ __forceinline__ float k2f(unsigned k) {
    unsigned u = (k & 0x80000000u) ? (k & 0x7fffffffu) : ~k;
    return __uint_as_float(u);
}

__global__ void topk_kernel(float* __restrict__ z_out)
{
    extern __shared__ unsigned skeys[];          // DSAE * 4 = 64 KB
    __shared__ unsigned hist[256];
    __shared__ int s_digit, s_take, s_cnt;

    const int b   = blockIdx.x;
    const int tid = threadIdx.x;
    const float* row = g_pre + (size_t)b * DSAE;

    for (int e = tid; e < DSAE; e += 256) skeys[e] = f2k(row[e]);
    if (tid == 0) { s_cnt = 0; g_bcnt[b] = 0; }
    __syncthreads();

    unsigned prefix = 0;
    int k_rem = KTOP;
#pragma unroll
    for (int r = 0; r < 4; r++) {
        const int shift = 24 - 8 * r;
        hist[tid] = 0;
        __syncthreads();
        for (int e = tid; e < DSAE; e += 256) {
            const unsigned key = skeys[e];
            if (r == 0 || (key >> (shift + 8)) == prefix)
                atomicAdd(&hist[(key >> shift) & 255u], 1u);
        }
        __syncthreads();
        if (tid == 0) {
            int c = 0, d;
            for (d = 255; d > 0; --d) {
                const int h = (int)hist[d];
                if (c + h >= k_rem) break;
                c += h;
            }
            s_digit = d;
            s_take  = k_rem - c;
        }
        __syncthreads();
        prefix = (prefix << 8) | (unsigned)s_digit;
        k_rem  = s_take;
        __syncthreads();
    }

    const float kv     = k2f(prefix);   // approx 64th-largest value
    const float hi_thr = kv + DELTA;
    const float lo_thr = kv - DELTA;

    for (int e = tid; e < DSAE; e += 256) {
        const float v = k2f(skeys[e]);
        if (v > hi_thr) {
            // certainly in exact top-64 (approx error << DELTA)
            const float zv = fmaxf(v, 0.f);
            z_out[(size_t)b * DSAE + e] = zv;
            const int p = atomicAdd(&s_cnt, 1);
            g_idx[b * KTOP + p] = e;
            g_val[b * KTOP + p] = zv;
        } else {
            z_out[(size_t)b * DSAE + e] = 0.f;   // band entries fixed up later
            if (v >= lo_thr) {
                const int q = atomicAdd(&g_bcnt[b], 1);
                if (q < MAXB) g_bidx[b][q] = e;
            }
        }
    }
    __syncthreads();
    if (tid == 0) g_scnt[b] = s_cnt;
}

// ---------------------------------------------------------------------------
// Kernel 3: exact rescoring of band candidates
// grid (MAXB, BSZ); one block per (slot,row); exact fp32 dot + bias.
// ---------------------------------------------------------------------------
__global__ __launch_bounds__(256)
void rescore_kernel(const float* __restrict__ x,
                    const float* __restrict__ W,
                    const float* __restrict__ bias)
{
    const int slot = blockIdx.x;
    const int b    = blockIdx.y;
    int cnt = g_bcnt[b];
    if (cnt > MAXB) cnt = MAXB;
    if (slot >= cnt) return;

    __shared__ float wsum[8];
    const int tid  = threadIdx.x;
    const int col  = g_bidx[b][slot];
    const float* xr = x + (size_t)b * KDIM;
    const float* wc = W + col;

    float s = 0.f;
#pragma unroll
    for (int i = 0; i < KDIM / 256; i++) {
        const int k = tid + i * 256;
        s = fmaf(xr[k], __ldg(&wc[(size_t)k * DSAE]), s);
    }
#pragma unroll
    for (int o = 16; o > 0; o >>= 1) s += __shfl_down_sync(0xffffffffu, s, o);
    if ((tid & 31) == 0) wsum[tid >> 5] = s;
    __syncthreads();
    if (tid == 0) {
        float tot = 0.f;
#pragma unroll
        for (int w = 0; w < 8; w++) tot += wsum[w];
        g_bval[b][slot] = tot + bias[col];
    }
}

// ---------------------------------------------------------------------------
// Kernel 4: fixup — rank band entries by exact score, fill remaining slots
// ---------------------------------------------------------------------------
__global__ __launch_bounds__(MAXB)
void fixup_kernel(float* __restrict__ z_out)
{
    __shared__ int   bi[MAXB];
    __shared__ float bv[MAXB];

    const int b   = blockIdx.x;
    const int tid = threadIdx.x;
    int cnt = g_bcnt[b];
    if (cnt > MAXB) cnt = MAXB;
    const int scnt = g_scnt[b];
    const int rem  = KTOP - scnt;

    if (tid < cnt) { bi[tid] = g_bidx[b][tid]; bv[tid] = g_bval[b][tid]; }
    __syncthreads();

    if (tid < cnt) {
        const int   mi = bi[tid];
        const float mv = bv[tid];
        int rank = 0;
        for (int j = 0; j < cnt; j++)
            rank += (bv[j] > mv) || (bv[j] == mv && bi[j] < mi);
        if (rank < rem) {
            const float zv = fmaxf(mv, 0.f);
            z_out[(size_t)b * DSAE + mi] = zv;
            const int pos = scnt + rank;
            g_idx[b * KTOP + pos] = mi;
            g_val[b * KTOP + pos] = zv;
        }
    }
}

// ---------------------------------------------------------------------------
// Kernel 5: sparse decode + basis combine + x_hat + loss
// ---------------------------------------------------------------------------
__global__ __launch_bounds__(256)
void decode_kernel(const float* __restrict__ x,
                   const float* __restrict__ Wb,
                   const float* __restrict__ alpha,
                   const float* __restrict__ b_dec,
                   float* __restrict__ xhat,
                   float* __restrict__ loss)
{
    __shared__ int   sidx[KTOP];
    __shared__ float sval[KTOP];
    __shared__ float salpha[TDIM * KBASIS];
    __shared__ float warpsum[8];

    const int b = blockIdx.x, tid = threadIdx.x;
    if (tid < KTOP)          { sidx[tid] = g_idx[b * KTOP + tid]; sval[tid] = g_val[b * KTOP + tid]; }
    if (tid < TDIM * KBASIS) { salpha[tid] = alpha[tid]; }
    __syncthreads();

    float acc[KBASIS][3];
#pragma unroll
    for (int k3 = 0; k3 < KBASIS; k3++)
#pragma unroll
        for (int dd = 0; dd < 3; dd++) acc[k3][dd] = 0.f;

    for (int j = 0; j < KTOP; j++) {
        const float v = sval[j];
        if (v == 0.f) continue;
        const int s = sidx[j];
        const float* wr = Wb + (size_t)s * DIN;
#pragma unroll
        for (int k3 = 0; k3 < KBASIS; k3++) {
            const float* w = wr + (size_t)k3 * DSAE * DIN;
#pragma unroll
            for (int dd = 0; dd < 3; dd++)
                acc[k3][dd] = fmaf(v, __ldg(&w[tid + dd * 256]), acc[k3][dd]);
        }
    }

    float lsum = 0.f;
#pragma unroll
    for (int t = 0; t < TDIM; t++) {
        const float a0 = salpha[t * KBASIS + 0];
        const float a1 = salpha[t * KBASIS + 1];
        const float a2 = salpha[t * KBASIS + 2];
#pragma unroll
        for (int dd = 0; dd < 3; dd++) {
            const int d = tid + dd * 256;
            const size_t off = ((size_t)b * TDIM + t) * DIN + d;
            const float xh = a0 * acc[0][dd] + a1 * acc[1][dd] + a2 * acc[2][dd]
                           + b_dec[t * DIN + d];
            xhat[off] = xh;
            const float diff = xh - x[off];
            lsum = fmaf(diff, diff, lsum);
        }
    }

#pragma unroll
    for (int o = 16; o > 0; o >>= 1) lsum += __shfl_down_sync(0xffffffffu, lsum, o);
    if ((tid & 31) == 0) warpsum[tid >> 5] = lsum;
    __syncthreads();
    if (tid == 0) {
        float s = 0.f;
#pragma unroll
        for (int w = 0; w < 8; w++) s += warpsum[w];
        atomicAdd(loss, s * (1.0f / (float)(BSZ * TDIM)));
    }
}

// ---------------------------------------------------------------------------
// kernel_launch: inputs = [x, W_enc, b_enc, W_base, alpha, b_dec, k]
// output (f32, concat): [recon_loss(1), x_hat(B*T*DIN), z(B*DSAE)]
// ---------------------------------------------------------------------------
extern "C" void kernel_launch(void* const* d_in, const int* in_sizes, int n_in,
                              void* d_out, int out_size)
{
    const float* x      = (const float*)d_in[0];
    const float* W_enc  = (const float*)d_in[1];
    const float* b_enc  = (const float*)d_in[2];
    const float* W_base = (const float*)d_in[3];
    const float* alpha  = (const float*)d_in[4];
    const float* b_dec  = (const float*)d_in[5];

    float* out  = (float*)d_out;
    float* loss = out;
    float* xhat = out + 1;
    float* z    = out + 1 + (size_t)BSZ * TDIM * DIN;

    cudaMemsetAsync(loss, 0, sizeof(float));

    const int gemm_smem = SM_TOTAL_F * (int)sizeof(float);   // 41984 B
    cudaFuncSetAttribute(enc_gemm,
                         cudaFuncAttributeMaxDynamicSharedMemorySize, gemm_smem);
    dim3 gemm_grid(BSZ / 128, DSAE / 128);   // (8, 128): M fast-varying
    enc_gemm<<<gemm_grid, 256, gemm_smem>>>(x, W_enc, b_enc);

    cudaFuncSetAttribute(topk_kernel,
                         cudaFuncAttributeMaxDynamicSharedMemorySize,
                         DSAE * (int)sizeof(unsigned));
    topk_kernel<<<BSZ, 256, DSAE * sizeof(unsigned)>>>(z);

    rescore_kernel<<<dim3(MAXB, BSZ), 256>>>(x, W_enc, b_enc);
    fixup_kernel<<<BSZ, MAXB>>>(z);

    decode_kernel<<<BSZ, 256>>>(x, W_base, alpha, b_dec, xhat, loss);
}